// round 4
// baseline (speedup 1.0000x reference)
#include <cuda_runtime.h>
#include <cstdint>
#include <cstddef>

// ============================================================================
// QuantumCoherentLayer — collapsed algebra (base sm_103 target: mma.sync tf32,
// cp.async; NO tcgen05/TMA — those are 'a'-gated and ptxas here targets sm_103).
//
//   w[j]  = sum_i softmax_row_i(cos(phase * J_sym))[j]
//   alpha = clip(exp(-t/51), 0, 1)
//   W_eff = sum_j w[j] * W_paths[j]                  (1024x1024)
//   M     = W_input @ W_eff                          (1024x1024)
//   out   = (a^2/64) * sum_j w[j]*coherent[:,j,:] + (a(1-a)/64) * (x @ M)
//
// k_scalars -> k_wet (WeT = weighted transpose) -> GEMM1 (Mt) -> GEMM2(+epi)
// GEMMs: C[i][j] = A[i,:].B[j,:], both K-major, mma.sync.m16n8k8 tf32,
// cp.async 3-stage pipeline, conflict-free LDS.128 via k-slot remapping.
// ============================================================================

#define PI_F 3.14159265358979323846f

static constexpr int H = 1024;
static constexpr int STAGES = 3;
static constexpr int KTILE = 32;
static constexpr int NKC = H / KTILE;   // 32

// ---------------- device scratch (no cudaMalloc allowed) ---------------------
__device__ float g_w[8];
__device__ float g_c[2];          // c1 = a^2/64, c2 = a(1-a)/64
__device__ float g_WeT[H * H];    // WeT[n][h] = W_eff[h][n]
__device__ float g_Mt[H * H];     // Mt[n][d]  = M[d][n]

// ---------------- small asm helpers ------------------------------------------
__device__ __forceinline__ uint32_t smem_u32(const void* p) {
    uint32_t a;
    asm("{ .reg .u64 t; cvta.to.shared.u64 t, %1; cvt.u32.u64 %0, t; }" : "=r"(a) : "l"(p));
    return a;
}
__device__ __forceinline__ void cp16(uint32_t s, const void* g) {
    asm volatile("cp.async.cg.shared.global [%0], [%1], 16;" :: "r"(s), "l"(g) : "memory");
}
#define CP_COMMIT() asm volatile("cp.async.commit_group;" ::: "memory")
#define CP_WAIT(n)  asm volatile("cp.async.wait_group %0;" :: "n"(n) : "memory")

__device__ __forceinline__ uint32_t f2tf(float f) {
    uint32_t r;
    asm("cvt.rna.tf32.f32 %0, %1;" : "=r"(r) : "f"(f));
    return r;
}
__device__ __forceinline__ void mma8(float* d, const uint32_t* a, const uint32_t* b) {
    asm volatile(
        "mma.sync.aligned.m16n8k8.row.col.f32.tf32.tf32.f32 "
        "{%0,%1,%2,%3}, {%4,%5,%6,%7}, {%8,%9}, {%0,%1,%2,%3};"
        : "+f"(d[0]), "+f"(d[1]), "+f"(d[2]), "+f"(d[3])
        : "r"(a[0]), "r"(a[1]), "r"(a[2]), "r"(a[3]), "r"(b[0]), "r"(b[1]));
}

// ============================================================================
// Kernel 1: scalars
// ============================================================================
__global__ void k_scalars(const float* __restrict__ J, const float* __restrict__ t) {
    __shared__ float S[8][8];
    __shared__ float R[8][8];
    int tid = threadIdx.x;
    float tv = t[0];
    float phase = 2.0f * PI_F * 20.0f * tv / 1000.0f;
    if (tid < 64) {
        int i = tid >> 3, j = tid & 7;
        S[i][j] = cosf(phase * 0.5f * (J[i * 8 + j] + J[j * 8 + i]));
    }
    __syncthreads();
    if (tid < 8) {
        int i = tid;
        float mx = -1e30f;
        #pragma unroll
        for (int j = 0; j < 8; j++) mx = fmaxf(mx, S[i][j]);
        float e[8], s = 0.0f;
        #pragma unroll
        for (int j = 0; j < 8; j++) { e[j] = expf(S[i][j] - mx); s += e[j]; }
        float inv = 1.0f / s;
        #pragma unroll
        for (int j = 0; j < 8; j++) R[i][j] = e[j] * inv;
    }
    __syncthreads();
    if (tid < 8) {
        int j = tid;
        float w = 0.0f;
        #pragma unroll
        for (int i = 0; i < 8; i++) w += R[i][j];
        g_w[j] = w;
    }
    if (tid == 0) {
        float a = expf(-tv / 51.0f);
        a = fminf(fmaxf(a, 0.0f), 1.0f);
        g_c[0] = a * a / 64.0f;
        g_c[1] = a * (1.0f - a) / 64.0f;
    }
}

// ============================================================================
// Kernel 2: WeT[n][h] = sum_j w[j] * W_paths[j][h][n]   (weighted transpose)
// ============================================================================
__global__ void k_wet(const float* __restrict__ Wp) {
    __shared__ float tile[32][33];
    float w[8];
    #pragma unroll
    for (int j = 0; j < 8; j++) w[j] = g_w[j];
    int h0 = blockIdx.x * 32, n0 = blockIdx.y * 32;
    int tx = threadIdx.x, ty = threadIdx.y;
    #pragma unroll
    for (int r = ty; r < 32; r += 8) {
        const float* p = Wp + (size_t)(h0 + r) * H + n0 + tx;
        float acc = 0.0f;
        #pragma unroll
        for (int j = 0; j < 8; j++) acc += w[j] * p[(size_t)j * H * H];
        tile[r][tx] = acc;
    }
    __syncthreads();
    #pragma unroll
    for (int r = ty; r < 32; r += 8)
        g_WeT[(size_t)(n0 + r) * H + h0 + tx] = tile[tx][r];
}

// ============================================================================
// Tiled GEMM: C[i][j] = sum_k A[i][k]*B[j][k]   (A:[M,1024], B:[N=1024 rows,1024])
//   CTA tile BM x 128, warp tile 32x64, warp grid WGM x WGN, 3-stage cp.async.
//   k-slot remapping: mma k-step (sp,u) slot c/h <-> gmem k = 16sp+4c+2u+h.
//   SMEM tiles [row][32k] fp32, 128B rows, chunk swizzle ch ^= 4*(row&1)
//   -> all fragment reads are conflict-free LDS.128.
//   EPI==0: C stored raw.  EPI==1: C = c2*C + c1*sum_j w[j]*coh[row][j][col].
// ============================================================================
template <int BM, int WGM, int WGN, int EPI>
__global__ void __launch_bounds__(WGM * WGN * 32, 1)
k_gemm(const float* __restrict__ A, const float* __restrict__ Bm,
       float* __restrict__ out, const float* __restrict__ coh) {
    constexpr int T = WGM * WGN * 32;
    constexpr int BN = 128;
    constexpr int ABYTES = BM * 128;        // BM rows x 32 f32
    constexpr int BBYTES = BN * 128;
    constexpr int STAGE_BYTES = ABYTES + BBYTES;

    extern __shared__ char smem[];
    uint32_t sbase = smem_u32(smem);

    int tid = threadIdx.x;
    int wid = tid >> 5, l = tid & 31;
    int wm = wid % WGM, wn = wid / WGM;
    int m0 = blockIdx.y * BM;
    int n0 = blockIdx.x * BN;
    int g = l >> 2, c = l & 3;
    int p4 = (g & 1) * 4;

    const float* gA = A + (size_t)m0 * H;
    const float* gB = Bm + (size_t)n0 * H;

    // issue cp.async for a full stage
    auto load_stage = [&](int kc, int stage) {
        uint32_t sA = sbase + stage * STAGE_BYTES;
        uint32_t sB = sA + ABYTES;
        const float* pA = gA + kc * KTILE;
        const float* pB = gB + kc * KTILE;
        #pragma unroll
        for (int i = tid; i < BM * 8; i += T) {
            int r = i >> 3, ch = i & 7;
            cp16(sA + r * 128 + ((ch ^ ((r & 1) * 4)) << 4), pA + (size_t)r * H + ch * 4);
        }
        #pragma unroll
        for (int i = tid; i < BN * 8; i += T) {
            int r = i >> 3, ch = i & 7;
            cp16(sB + r * 128 + ((ch ^ ((r & 1) * 4)) << 4), pB + (size_t)r * H + ch * 4);
        }
    };

    #pragma unroll
    for (int s = 0; s < STAGES - 1; s++) { load_stage(s, s); CP_COMMIT(); }

    float acc[2][8][4];
    #pragma unroll
    for (int mf = 0; mf < 2; mf++)
        #pragma unroll
        for (int f = 0; f < 8; f++)
            #pragma unroll
            for (int q = 0; q < 4; q++) acc[mf][f][q] = 0.0f;

    int rowA = wm * 32 + g;   // within tile
    int rowB = wn * 64 + g;

    for (int kc = 0; kc < NKC; kc++) {
        CP_WAIT(STAGES - 2);
        __syncthreads();
        int stage = kc % STAGES;
        const char* tA = smem + stage * STAGE_BYTES;
        const char* tB = tA + ABYTES;

        #pragma unroll
        for (int sp = 0; sp < 2; sp++) {
            int ch = (4 * sp + c) ^ p4;
            uint32_t av[4][4];
            #pragma unroll
            for (int rr = 0; rr < 4; rr++) {
                float4 v = *(const float4*)(tA + (rowA + rr * 8) * 128 + ch * 16);
                av[rr][0] = f2tf(v.x); av[rr][1] = f2tf(v.y);
                av[rr][2] = f2tf(v.z); av[rr][3] = f2tf(v.w);
            }
            uint32_t bv[8][4];
            #pragma unroll
            for (int f = 0; f < 8; f++) {
                float4 v = *(const float4*)(tB + (rowB + f * 8) * 128 + ch * 16);
                bv[f][0] = f2tf(v.x); bv[f][1] = f2tf(v.y);
                bv[f][2] = f2tf(v.z); bv[f][3] = f2tf(v.w);
            }
            #pragma unroll
            for (int u = 0; u < 2; u++) {
                #pragma unroll
                for (int mf = 0; mf < 2; mf++) {
                    uint32_t a[4] = { av[2 * mf][2 * u],     av[2 * mf + 1][2 * u],
                                      av[2 * mf][2 * u + 1], av[2 * mf + 1][2 * u + 1] };
                    #pragma unroll
                    for (int f = 0; f < 8; f++) {
                        uint32_t b[2] = { bv[f][2 * u], bv[f][2 * u + 1] };
                        mma8(acc[mf][f], a, b);
                    }
                }
            }
        }
        if (kc + STAGES - 1 < NKC) load_stage(kc + STAGES - 1, (kc + STAGES - 1) % STAGES);
        CP_COMMIT();
    }

    // ----------------- epilogue -----------------
    float c1 = 0.f, c2 = 0.f, w[8];
    if (EPI) {
        c1 = g_c[0]; c2 = g_c[1];
        #pragma unroll
        for (int j = 0; j < 8; j++) w[j] = g_w[j];
    }
    #pragma unroll
    for (int mf = 0; mf < 2; mf++) {
        #pragma unroll
        for (int hh = 0; hh < 2; hh++) {
            int row = m0 + wm * 32 + mf * 16 + hh * 8 + g;
            #pragma unroll
            for (int f = 0; f < 8; f++) {
                int col = n0 + wn * 64 + f * 8 + 2 * c;
                float v0 = acc[mf][f][2 * hh];
                float v1 = acc[mf][f][2 * hh + 1];
                if (EPI) {
                    float s0 = 0.f, s1 = 0.f;
                    const float* cp = coh + ((size_t)row * 8) * H + col;
                    #pragma unroll
                    for (int j = 0; j < 8; j++) {
                        float2 cv = *(const float2*)(cp + (size_t)j * H);
                        s0 += w[j] * cv.x;
                        s1 += w[j] * cv.y;
                    }
                    v0 = c2 * v0 + c1 * s0;
                    v1 = c2 * v1 + c1 * s1;
                }
                *(float2*)(out + (size_t)row * H + col) = make_float2(v0, v1);
            }
        }
    }
}

// ============================================================================
// Host side
// ============================================================================
extern "C" void kernel_launch(void* const* d_in, const int* in_sizes, int n_in,
                              void* d_out, int out_size) {
    const float* x   = (const float*)d_in[0];   // [2048, 1024]
    const float* Wi  = (const float*)d_in[1];   // [1024, 1024]
    const float* Wp  = (const float*)d_in[2];   // [8, 1024, 1024]
    const float* J   = (const float*)d_in[3];   // [8, 8]
    const float* coh = (const float*)d_in[4];   // [2048, 8, 1024]
    const float* t   = (const float*)d_in[5];   // [1]
    float* out = (float*)d_out;                 // [2048, 1024]
    (void)in_sizes; (void)n_in; (void)out_size;

    void* we_ptr = nullptr;
    void* mt_ptr = nullptr;
    cudaGetSymbolAddress(&we_ptr, g_WeT);
    cudaGetSymbolAddress(&mt_ptr, g_Mt);

    constexpr int SMEM1 = STAGES * (64 * 128 + 128 * 128);    // 72 KB
    constexpr int SMEM2 = STAGES * (128 * 128 + 128 * 128);   // 96 KB
    cudaFuncSetAttribute((const void*)k_gemm<64, 2, 2, 0>,
                         cudaFuncAttributeMaxDynamicSharedMemorySize, SMEM1);
    cudaFuncSetAttribute((const void*)k_gemm<128, 4, 2, 1>,
                         cudaFuncAttributeMaxDynamicSharedMemorySize, SMEM2);

    k_scalars<<<1, 64>>>(J, t);
    k_wet<<<dim3(32, 32), dim3(32, 8)>>>(Wp);
    // GEMM1: Mt[n][d] = sum_h WeT[n][h] * Wi[d][h]   -> 16x8 grid of 64x128 tiles
    k_gemm<64, 2, 2, 0><<<dim3(8, 16), 128, SMEM1>>>(
        (const float*)we_ptr, Wi, (float*)mt_ptr, nullptr);
    // GEMM2: out[b][n] = c2 * sum_d x[b][d]*Mt[n][d] + c1 * sum_j w[j]*coh[b][j][n]
    k_gemm<128, 4, 2, 1><<<dim3(8, 16), 256, SMEM2>>>(
        x, (const float*)mt_ptr, out, coh);
}

// round 6
// speedup vs baseline: 1.1800x; 1.1800x over previous
#include <cuda_runtime.h>
#include <cstdint>
#include <cstddef>

// ============================================================================
// QuantumCoherentLayer — collapsed algebra (base sm_103 target: mma.sync tf32,
// cp.async; NO tcgen05/TMA — those are 'a'-gated and ptxas here targets sm_103).
//
//   w[j]  = sum_i softmax_row_i(cos(phase * J_sym))[j]
//   alpha = clip(exp(-t/51), 0, 1)
//   W_eff = sum_j w[j] * W_paths[j]                  (1024x1024)
//   M     = W_input @ W_eff                          (1024x1024)
//   out   = (a^2/64) * sum_j w[j]*coherent[:,j,:] + (a(1-a)/64) * (x @ M)
//
// R5 change vs R4: NO explicit cvt.rna.tf32 — HMMA reads fp32 registers and
// truncates to tf32 in HW. ncu showed GEMM2 alu=43.4% > tensor=23.6%: the 96
// cvts per warp per k-tile were ~half the issue stream. Removing them also
// drops the cvt temp arrays (regs were 255).
// ============================================================================

#define PI_F 3.14159265358979323846f

static constexpr int H = 1024;
static constexpr int STAGES = 3;
static constexpr int KTILE = 32;
static constexpr int NKC = H / KTILE;   // 32

// ---------------- device scratch (no cudaMalloc allowed) ---------------------
__device__ float g_w[8];
__device__ float g_c[2];          // c1 = a^2/64, c2 = a(1-a)/64
__device__ float g_WeT[H * H];    // WeT[n][h] = W_eff[h][n]
__device__ float g_Mt[H * H];     // Mt[n][d]  = M[d][n]

// ---------------- small asm helpers ------------------------------------------
__device__ __forceinline__ uint32_t smem_u32(const void* p) {
    uint32_t a;
    asm("{ .reg .u64 t; cvta.to.shared.u64 t, %1; cvt.u32.u64 %0, t; }" : "=r"(a) : "l"(p));
    return a;
}
__device__ __forceinline__ void cp16(uint32_t s, const void* g) {
    asm volatile("cp.async.cg.shared.global [%0], [%1], 16;" :: "r"(s), "l"(g) : "memory");
}
#define CP_COMMIT() asm volatile("cp.async.commit_group;" ::: "memory")
#define CP_WAIT(n)  asm volatile("cp.async.wait_group %0;" :: "n"(n) : "memory")

__device__ __forceinline__ void mma8(float* d, const uint32_t* a, const uint32_t* b) {
    asm volatile(
        "mma.sync.aligned.m16n8k8.row.col.f32.tf32.tf32.f32 "
        "{%0,%1,%2,%3}, {%4,%5,%6,%7}, {%8,%9}, {%0,%1,%2,%3};"
        : "+f"(d[0]), "+f"(d[1]), "+f"(d[2]), "+f"(d[3])
        : "r"(a[0]), "r"(a[1]), "r"(a[2]), "r"(a[3]), "r"(b[0]), "r"(b[1]));
}

// ============================================================================
// Kernel 1: scalars
// ============================================================================
__global__ void k_scalars(const float* __restrict__ J, const float* __restrict__ t) {
    __shared__ float S[8][8];
    __shared__ float R[8][8];
    int tid = threadIdx.x;
    float tv = t[0];
    float phase = 2.0f * PI_F * 20.0f * tv / 1000.0f;
    if (tid < 64) {
        int i = tid >> 3, j = tid & 7;
        S[i][j] = cosf(phase * 0.5f * (J[i * 8 + j] + J[j * 8 + i]));
    }
    __syncthreads();
    if (tid < 8) {
        int i = tid;
        float mx = -1e30f;
        #pragma unroll
        for (int j = 0; j < 8; j++) mx = fmaxf(mx, S[i][j]);
        float e[8], s = 0.0f;
        #pragma unroll
        for (int j = 0; j < 8; j++) { e[j] = expf(S[i][j] - mx); s += e[j]; }
        float inv = 1.0f / s;
        #pragma unroll
        for (int j = 0; j < 8; j++) R[i][j] = e[j] * inv;
    }
    __syncthreads();
    if (tid < 8) {
        int j = tid;
        float w = 0.0f;
        #pragma unroll
        for (int i = 0; i < 8; i++) w += R[i][j];
        g_w[j] = w;
    }
    if (tid == 0) {
        float a = expf(-tv / 51.0f);
        a = fminf(fmaxf(a, 0.0f), 1.0f);
        g_c[0] = a * a / 64.0f;
        g_c[1] = a * (1.0f - a) / 64.0f;
    }
}

// ============================================================================
// Kernel 2: WeT[n][h] = sum_j w[j] * W_paths[j][h][n]   (weighted transpose)
// ============================================================================
__global__ void k_wet(const float* __restrict__ Wp) {
    __shared__ float tile[32][33];
    float w[8];
    #pragma unroll
    for (int j = 0; j < 8; j++) w[j] = g_w[j];
    int h0 = blockIdx.x * 32, n0 = blockIdx.y * 32;
    int tx = threadIdx.x, ty = threadIdx.y;
    #pragma unroll
    for (int r = ty; r < 32; r += 8) {
        const float* p = Wp + (size_t)(h0 + r) * H + n0 + tx;
        float acc = 0.0f;
        #pragma unroll
        for (int j = 0; j < 8; j++) acc += w[j] * p[(size_t)j * H * H];
        tile[r][tx] = acc;
    }
    __syncthreads();
    #pragma unroll
    for (int r = ty; r < 32; r += 8)
        g_WeT[(size_t)(n0 + r) * H + h0 + tx] = tile[tx][r];
}

// ============================================================================
// Tiled GEMM: C[i][j] = sum_k A[i][k]*B[j][k]   (A:[M,1024], B:[N=1024 rows,1024])
//   CTA tile BM x 128, warp tile 32x64, warp grid WGM x WGN, 3-stage cp.async.
//   k-slot remapping: mma k-step (sp,u) slot c/h <-> gmem k = 16sp+4c+2u+h.
//   SMEM tiles [row][32k] fp32, 128B rows, chunk swizzle ch ^= 4*(row&1)
//   -> all fragment reads are conflict-free LDS.128.
//   Operands fed to HMMA as raw fp32 bits (HW-truncated tf32; no cvt).
//   EPI==0: C stored raw.  EPI==1: C = c2*C + c1*sum_j w[j]*coh[row][j][col].
// ============================================================================
template <int BM, int WGM, int WGN, int EPI>
__global__ void __launch_bounds__(WGM * WGN * 32, 1)
k_gemm(const float* __restrict__ A, const float* __restrict__ Bm,
       float* __restrict__ out, const float* __restrict__ coh) {
    constexpr int T = WGM * WGN * 32;
    constexpr int BN = 128;
    constexpr int ABYTES = BM * 128;        // BM rows x 32 f32
    constexpr int BBYTES = BN * 128;
    constexpr int STAGE_BYTES = ABYTES + BBYTES;

    extern __shared__ char smem[];
    uint32_t sbase = smem_u32(smem);

    int tid = threadIdx.x;
    int wid = tid >> 5, l = tid & 31;
    int wm = wid % WGM, wn = wid / WGM;
    int m0 = blockIdx.y * BM;
    int n0 = blockIdx.x * BN;
    int g = l >> 2, c = l & 3;
    int p4 = (g & 1) * 4;

    const float* gA = A + (size_t)m0 * H;
    const float* gB = Bm + (size_t)n0 * H;

    // issue cp.async for a full stage
    auto load_stage = [&](int kc, int stage) {
        uint32_t sA = sbase + stage * STAGE_BYTES;
        uint32_t sB = sA + ABYTES;
        const float* pA = gA + kc * KTILE;
        const float* pB = gB + kc * KTILE;
        #pragma unroll
        for (int i = tid; i < BM * 8; i += T) {
            int r = i >> 3, ch = i & 7;
            cp16(sA + r * 128 + ((ch ^ ((r & 1) * 4)) << 4), pA + (size_t)r * H + ch * 4);
        }
        #pragma unroll
        for (int i = tid; i < BN * 8; i += T) {
            int r = i >> 3, ch = i & 7;
            cp16(sB + r * 128 + ((ch ^ ((r & 1) * 4)) << 4), pB + (size_t)r * H + ch * 4);
        }
    };

    #pragma unroll
    for (int s = 0; s < STAGES - 1; s++) { load_stage(s, s); CP_COMMIT(); }

    float acc[2][8][4];
    #pragma unroll
    for (int mf = 0; mf < 2; mf++)
        #pragma unroll
        for (int f = 0; f < 8; f++)
            #pragma unroll
            for (int q = 0; q < 4; q++) acc[mf][f][q] = 0.0f;

    int rowA = wm * 32 + g;   // within tile
    int rowB = wn * 64 + g;

    for (int kc = 0; kc < NKC; kc++) {
        CP_WAIT(STAGES - 2);
        __syncthreads();
        int stage = kc % STAGES;
        const char* tA = smem + stage * STAGE_BYTES;
        const char* tB = tA + ABYTES;

        #pragma unroll
        for (int sp = 0; sp < 2; sp++) {
            int ch = (4 * sp + c) ^ p4;
            uint4 av[4];
            #pragma unroll
            for (int rr = 0; rr < 4; rr++)
                av[rr] = *(const uint4*)(tA + (rowA + rr * 8) * 128 + ch * 16);
            uint4 bv[8];
            #pragma unroll
            for (int f = 0; f < 8; f++)
                bv[f] = *(const uint4*)(tB + (rowB + f * 8) * 128 + ch * 16);
            #pragma unroll
            for (int u = 0; u < 2; u++) {
                #pragma unroll
                for (int mf = 0; mf < 2; mf++) {
                    uint32_t a[4];
                    if (u == 0) {
                        a[0] = av[2 * mf].x;     a[1] = av[2 * mf + 1].x;
                        a[2] = av[2 * mf].y;     a[3] = av[2 * mf + 1].y;
                    } else {
                        a[0] = av[2 * mf].z;     a[1] = av[2 * mf + 1].z;
                        a[2] = av[2 * mf].w;     a[3] = av[2 * mf + 1].w;
                    }
                    #pragma unroll
                    for (int f = 0; f < 8; f++) {
                        uint32_t b[2];
                        if (u == 0) { b[0] = bv[f].x; b[1] = bv[f].y; }
                        else        { b[0] = bv[f].z; b[1] = bv[f].w; }
                        mma8(acc[mf][f], a, b);
                    }
                }
            }
        }
        if (kc + STAGES - 1 < NKC) load_stage(kc + STAGES - 1, (kc + STAGES - 1) % STAGES);
        CP_COMMIT();
    }

    // ----------------- epilogue -----------------
    float c1 = 0.f, c2 = 0.f, w[8];
    if (EPI) {
        c1 = g_c[0]; c2 = g_c[1];
        #pragma unroll
        for (int j = 0; j < 8; j++) w[j] = g_w[j];
    }
    #pragma unroll
    for (int mf = 0; mf < 2; mf++) {
        #pragma unroll
        for (int hh = 0; hh < 2; hh++) {
            int row = m0 + wm * 32 + mf * 16 + hh * 8 + g;
            #pragma unroll
            for (int f = 0; f < 8; f++) {
                int col = n0 + wn * 64 + f * 8 + 2 * c;
                float v0 = acc[mf][f][2 * hh];
                float v1 = acc[mf][f][2 * hh + 1];
                if (EPI) {
                    float s0 = 0.f, s1 = 0.f;
                    const float* cp = coh + ((size_t)row * 8) * H + col;
                    #pragma unroll
                    for (int j = 0; j < 8; j++) {
                        float2 cv = *(const float2*)(cp + (size_t)j * H);
                        s0 += w[j] * cv.x;
                        s1 += w[j] * cv.y;
                    }
                    v0 = c2 * v0 + c1 * s0;
                    v1 = c2 * v1 + c1 * s1;
                }
                *(float2*)(out + (size_t)row * H + col) = make_float2(v0, v1);
            }
        }
    }
}

// ============================================================================
// Host side
// ============================================================================
extern "C" void kernel_launch(void* const* d_in, const int* in_sizes, int n_in,
                              void* d_out, int out_size) {
    const float* x   = (const float*)d_in[0];   // [2048, 1024]
    const float* Wi  = (const float*)d_in[1];   // [1024, 1024]
    const float* Wp  = (const float*)d_in[2];   // [8, 1024, 1024]
    const float* J   = (const float*)d_in[3];   // [8, 8]
    const float* coh = (const float*)d_in[4];   // [2048, 8, 1024]
    const float* t   = (const float*)d_in[5];   // [1]
    float* out = (float*)d_out;                 // [2048, 1024]
    (void)in_sizes; (void)n_in; (void)out_size;

    void* we_ptr = nullptr;
    void* mt_ptr = nullptr;
    cudaGetSymbolAddress(&we_ptr, g_WeT);
    cudaGetSymbolAddress(&mt_ptr, g_Mt);

    constexpr int SMEM1 = STAGES * (64 * 128 + 128 * 128);    // 72 KB
    constexpr int SMEM2 = STAGES * (128 * 128 + 128 * 128);   // 96 KB
    cudaFuncSetAttribute((const void*)k_gemm<64, 2, 2, 0>,
                         cudaFuncAttributeMaxDynamicSharedMemorySize, SMEM1);
    cudaFuncSetAttribute((const void*)k_gemm<128, 4, 2, 1>,
                         cudaFuncAttributeMaxDynamicSharedMemorySize, SMEM2);

    k_scalars<<<1, 64>>>(J, t);
    k_wet<<<dim3(32, 32), dim3(32, 8)>>>(Wp);
    // GEMM1: Mt[n][d] = sum_h WeT[n][h] * Wi[d][h]   -> 16x8 grid of 64x128 tiles
    k_gemm<64, 2, 2, 0><<<dim3(8, 16), 128, SMEM1>>>(
        (const float*)we_ptr, Wi, (float*)mt_ptr, nullptr);
    // GEMM2: out[b][n] = c2 * sum_d x[b][d]*Mt[n][d] + c1 * sum_j w[j]*coh[b][j][n]
    k_gemm<128, 4, 2, 1><<<dim3(8, 16), 256, SMEM2>>>(
        x, (const float*)mt_ptr, out, coh);
}

// round 7
// speedup vs baseline: 1.1978x; 1.0151x over previous
#include <cuda_runtime.h>
#include <cstdint>
#include <cstddef>

// ============================================================================
// QuantumCoherentLayer — collapsed algebra (base sm_103: mma.sync tf32 + cp.async)
//
//   w[j]  = sum_i softmax_row_i(cos(phase * J_sym))[j]
//   alpha = clip(exp(-t/51), 0, 1)
//   W_eff = sum_j w[j] * W_paths[j];  M = W_input @ W_eff
//   out   = (a^2/64)*sum_j w[j]*coherent[:,j,:] + (a(1-a)/64)*(x @ M)
//
// R6: ncu showed GEMM2 latency-exposed (issue 33%, occ 12.7%, regs 255, no pipe
// >32%). Changes: 16 warps x 32x32 warp tiles (512 thr) for GEMM2, 8 warps for
// GEMM1; STAGES=4 (stage = kc&3, unroll-by-4 => compile-time stage offsets);
// prefetch issued before compute; k_wet vectorized to float4.
// ============================================================================

#define PI_F 3.14159265358979323846f

static constexpr int H = 1024;
static constexpr int STAGES = 4;
static constexpr int KTILE = 32;
static constexpr int NKC = H / KTILE;   // 32

// ---------------- device scratch (no cudaMalloc allowed) ---------------------
__device__ float g_w[8];
__device__ float g_c[2];          // c1 = a^2/64, c2 = a(1-a)/64
__device__ float g_WeT[H * H];    // WeT[n][h] = W_eff[h][n]
__device__ float g_Mt[H * H];     // Mt[n][d]  = M[d][n]

// ---------------- asm helpers ------------------------------------------------
__device__ __forceinline__ uint32_t smem_u32(const void* p) {
    uint32_t a;
    asm("{ .reg .u64 t; cvta.to.shared.u64 t, %1; cvt.u32.u64 %0, t; }" : "=r"(a) : "l"(p));
    return a;
}
__device__ __forceinline__ void cp16(uint32_t s, const void* g) {
    asm volatile("cp.async.cg.shared.global [%0], [%1], 16;" :: "r"(s), "l"(g) : "memory");
}
#define CP_COMMIT() asm volatile("cp.async.commit_group;" ::: "memory")
#define CP_WAIT(n)  asm volatile("cp.async.wait_group %0;" :: "n"(n) : "memory")

__device__ __forceinline__ void mma8(float* d, const uint32_t* a, const uint32_t* b) {
    asm volatile(
        "mma.sync.aligned.m16n8k8.row.col.f32.tf32.tf32.f32 "
        "{%0,%1,%2,%3}, {%4,%5,%6,%7}, {%8,%9}, {%0,%1,%2,%3};"
        : "+f"(d[0]), "+f"(d[1]), "+f"(d[2]), "+f"(d[3])
        : "r"(a[0]), "r"(a[1]), "r"(a[2]), "r"(a[3]), "r"(b[0]), "r"(b[1]));
}

// ============================================================================
// Kernel 1: scalars
// ============================================================================
__global__ void k_scalars(const float* __restrict__ J, const float* __restrict__ t) {
    __shared__ float S[8][8];
    __shared__ float R[8][8];
    int tid = threadIdx.x;
    float tv = t[0];
    float phase = 2.0f * PI_F * 20.0f * tv / 1000.0f;
    if (tid < 64) {
        int i = tid >> 3, j = tid & 7;
        S[i][j] = cosf(phase * 0.5f * (J[i * 8 + j] + J[j * 8 + i]));
    }
    __syncthreads();
    if (tid < 8) {
        int i = tid;
        float mx = -1e30f;
        #pragma unroll
        for (int j = 0; j < 8; j++) mx = fmaxf(mx, S[i][j]);
        float e[8], s = 0.0f;
        #pragma unroll
        for (int j = 0; j < 8; j++) { e[j] = expf(S[i][j] - mx); s += e[j]; }
        float inv = 1.0f / s;
        #pragma unroll
        for (int j = 0; j < 8; j++) R[i][j] = e[j] * inv;
    }
    __syncthreads();
    if (tid < 8) {
        int j = tid;
        float w = 0.0f;
        #pragma unroll
        for (int i = 0; i < 8; i++) w += R[i][j];
        g_w[j] = w;
    }
    if (tid == 0) {
        float a = expf(-tv / 51.0f);
        a = fminf(fmaxf(a, 0.0f), 1.0f);
        g_c[0] = a * a / 64.0f;
        g_c[1] = a * (1.0f - a) / 64.0f;
    }
}

// ============================================================================
// Kernel 2: WeT[n][h] = sum_j w[j] * W_paths[j][h][n]  (weighted transpose)
// Tile: 32 h-rows x 128 n-cols, float4 loads, padded smem transpose.
// ============================================================================
__global__ void __launch_bounds__(256) k_wet(const float* __restrict__ Wp) {
    __shared__ float tile[32][133];   // pad 133: gcd(133?,..)->col reads conflict-free
    float w[8];
    #pragma unroll
    for (int j = 0; j < 8; j++) w[j] = g_w[j];
    int h0 = blockIdx.x * 32, n0 = blockIdx.y * 128;
    int tid = threadIdx.x;

    // load+weight: 32 rows x 32 float4-chunks
    #pragma unroll
    for (int i = tid; i < 32 * 32; i += 256) {
        int r = i >> 5, c4 = i & 31;
        const float* p = Wp + (size_t)(h0 + r) * H + n0 + c4 * 4;
        float4 acc = make_float4(0.f, 0.f, 0.f, 0.f);
        #pragma unroll
        for (int j = 0; j < 8; j++) {
            float4 v = *(const float4*)(p + (size_t)j * H * H);
            acc.x += w[j] * v.x; acc.y += w[j] * v.y;
            acc.z += w[j] * v.z; acc.w += w[j] * v.w;
        }
        tile[r][c4 * 4 + 0] = acc.x;
        tile[r][c4 * 4 + 1] = acc.y;
        tile[r][c4 * 4 + 2] = acc.z;
        tile[r][c4 * 4 + 3] = acc.w;
    }
    __syncthreads();
    // store transposed: 128 n-rows x 32 h-cols
    #pragma unroll
    for (int i = tid; i < 128 * 32; i += 256) {
        int n = i >> 5, hc = i & 31;
        g_WeT[(size_t)(n0 + n) * H + h0 + hc] = tile[hc][n];
    }
}

// ============================================================================
// Tiled GEMM: C[i][j] = sum_k A[i][k]*B[j][k]  (A:[M,1024], B:[1024 rows,1024])
//   CTA tile BM x 128, warp tile 32x32, warp grid WGM x WGN, 4-stage cp.async.
//   k-slot remap: mma k-step (sp,u) slot c/h <-> k = 16sp+4c+2u+h (A/B agree).
//   SMEM [row][32k] f32 128B rows, chunk swizzle ch ^= 4*(row&1): LDS.128
//   conflict-free. Raw fp32 bits into HMMA (HW tf32 truncation).
//   EPI==0: raw store. EPI==1: C = c2*C + c1*sum_j w[j]*coh[row][j][col].
// ============================================================================
template <int BM, int WGM, int WGN, int EPI>
__global__ void __launch_bounds__(WGM * WGN * 32, 1)
k_gemm(const float* __restrict__ A, const float* __restrict__ Bm,
       float* __restrict__ out, const float* __restrict__ coh) {
    constexpr int T = WGM * WGN * 32;
    constexpr int BN = 128;
    constexpr int ABYTES = BM * 128;
    constexpr int BBYTES = BN * 128;
    constexpr int STAGE_BYTES = ABYTES + BBYTES;

    extern __shared__ char smem[];
    uint32_t sbase = smem_u32(smem);

    int tid = threadIdx.x;
    int wid = tid >> 5, l = tid & 31;
    int wm = wid % WGM, wn = wid / WGM;
    int m0 = blockIdx.y * BM;
    int n0 = blockIdx.x * BN;
    int g = l >> 2, c = l & 3;
    int p4 = (g & 1) * 4;

    const float* gA = A + (size_t)m0 * H;
    const float* gB = Bm + (size_t)n0 * H;

    auto load_stage = [&](int kc, int stage) {
        uint32_t sA = sbase + stage * STAGE_BYTES;
        uint32_t sB = sA + ABYTES;
        const float* pA = gA + kc * KTILE;
        const float* pB = gB + kc * KTILE;
        #pragma unroll
        for (int i = tid; i < BM * 8; i += T) {
            int r = i >> 3, ch = i & 7;
            cp16(sA + r * 128 + ((ch ^ ((r & 1) * 4)) << 4), pA + (size_t)r * H + ch * 4);
        }
        #pragma unroll
        for (int i = tid; i < BN * 8; i += T) {
            int r = i >> 3, ch = i & 7;
            cp16(sB + r * 128 + ((ch ^ ((r & 1) * 4)) << 4), pB + (size_t)r * H + ch * 4);
        }
    };

    #pragma unroll
    for (int s = 0; s < STAGES - 1; s++) { load_stage(s, s); CP_COMMIT(); }

    float acc[2][4][4];
    #pragma unroll
    for (int mf = 0; mf < 2; mf++)
        #pragma unroll
        for (int f = 0; f < 4; f++)
            #pragma unroll
            for (int q = 0; q < 4; q++) acc[mf][f][q] = 0.0f;

    int rowA = wm * 32 + g;
    int rowB = wn * 32 + g;

    #pragma unroll 1
    for (int kc0 = 0; kc0 < NKC; kc0 += 4) {
        #pragma unroll
        for (int s4 = 0; s4 < 4; s4++) {
            int kc = kc0 + s4;
            CP_WAIT(STAGES - 2);
            __syncthreads();
            // prefetch k-tile kc+3 into slot (kc+3)&3 == (kc-1)&3 (free: all
            // warps passed the sync after finishing kc-1's compute)
            if (kc + STAGES - 1 < NKC) load_stage(kc + STAGES - 1, (kc + STAGES - 1) & 3);
            CP_COMMIT();

            const char* tA = smem + s4 * STAGE_BYTES;
            const char* tB = tA + ABYTES;

            #pragma unroll
            for (int sp = 0; sp < 2; sp++) {
                int ch = (4 * sp + c) ^ p4;
                uint4 av[4];
                #pragma unroll
                for (int rr = 0; rr < 4; rr++)
                    av[rr] = *(const uint4*)(tA + (rowA + rr * 8) * 128 + ch * 16);
                uint4 bv[4];
                #pragma unroll
                for (int f = 0; f < 4; f++)
                    bv[f] = *(const uint4*)(tB + (rowB + f * 8) * 128 + ch * 16);
                #pragma unroll
                for (int u = 0; u < 2; u++) {
                    #pragma unroll
                    for (int mf = 0; mf < 2; mf++) {
                        uint32_t a[4];
                        if (u == 0) {
                            a[0] = av[2 * mf].x; a[1] = av[2 * mf + 1].x;
                            a[2] = av[2 * mf].y; a[3] = av[2 * mf + 1].y;
                        } else {
                            a[0] = av[2 * mf].z; a[1] = av[2 * mf + 1].z;
                            a[2] = av[2 * mf].w; a[3] = av[2 * mf + 1].w;
                        }
                        #pragma unroll
                        for (int f = 0; f < 4; f++) {
                            uint32_t b[2];
                            if (u == 0) { b[0] = bv[f].x; b[1] = bv[f].y; }
                            else        { b[0] = bv[f].z; b[1] = bv[f].w; }
                            mma8(acc[mf][f], a, b);
                        }
                    }
                }
            }
        }
    }

    // ----------------- epilogue -----------------
    float c1 = 0.f, c2 = 0.f, w[8];
    if (EPI) {
        c1 = g_c[0]; c2 = g_c[1];
        #pragma unroll
        for (int j = 0; j < 8; j++) w[j] = g_w[j];
    }
    #pragma unroll
    for (int mf = 0; mf < 2; mf++) {
        #pragma unroll
        for (int hh = 0; hh < 2; hh++) {
            int row = m0 + wm * 32 + mf * 16 + hh * 8 + g;
            #pragma unroll
            for (int f = 0; f < 4; f++) {
                int col = n0 + wn * 32 + f * 8 + 2 * c;
                float v0 = acc[mf][f][2 * hh];
                float v1 = acc[mf][f][2 * hh + 1];
                if (EPI) {
                    float s0 = 0.f, s1 = 0.f;
                    const float* cp = coh + ((size_t)row * 8) * H + col;
                    #pragma unroll
                    for (int j = 0; j < 8; j++) {
                        float2 cv = *(const float2*)(cp + (size_t)j * H);
                        s0 += w[j] * cv.x;
                        s1 += w[j] * cv.y;
                    }
                    v0 = c2 * v0 + c1 * s0;
                    v1 = c2 * v1 + c1 * s1;
                }
                *(float2*)(out + (size_t)row * H + col) = make_float2(v0, v1);
            }
        }
    }
}

// ============================================================================
// Host side
// ============================================================================
extern "C" void kernel_launch(void* const* d_in, const int* in_sizes, int n_in,
                              void* d_out, int out_size) {
    const float* x   = (const float*)d_in[0];   // [2048, 1024]
    const float* Wi  = (const float*)d_in[1];   // [1024, 1024]
    const float* Wp  = (const float*)d_in[2];   // [8, 1024, 1024]
    const float* J   = (const float*)d_in[3];   // [8, 8]
    const float* coh = (const float*)d_in[4];   // [2048, 8, 1024]
    const float* t   = (const float*)d_in[5];   // [1]
    float* out = (float*)d_out;                 // [2048, 1024]
    (void)in_sizes; (void)n_in; (void)out_size;

    void* we_ptr = nullptr;
    void* mt_ptr = nullptr;
    cudaGetSymbolAddress(&we_ptr, g_WeT);
    cudaGetSymbolAddress(&mt_ptr, g_Mt);

    constexpr int SMEM1 = STAGES * (64 * 128 + 128 * 128);    // 96 KB
    constexpr int SMEM2 = STAGES * (128 * 128 + 128 * 128);   // 128 KB
    cudaFuncSetAttribute((const void*)k_gemm<64, 2, 4, 0>,
                         cudaFuncAttributeMaxDynamicSharedMemorySize, SMEM1);
    cudaFuncSetAttribute((const void*)k_gemm<128, 4, 4, 1>,
                         cudaFuncAttributeMaxDynamicSharedMemorySize, SMEM2);

    k_scalars<<<1, 64>>>(J, t);
    k_wet<<<dim3(32, 8), 256>>>(Wp);
    // GEMM1: Mt[n][d] = sum_h WeT[n][h] * Wi[d][h]
    k_gemm<64, 2, 4, 0><<<dim3(8, 16), 256, SMEM1>>>(
        (const float*)we_ptr, Wi, (float*)mt_ptr, nullptr);
    // GEMM2: out[b][n] = c2 * sum_d x[b][d]*Mt[n][d] + c1 * sum_j w[j]*coh[b][j][n]
    k_gemm<128, 4, 4, 1><<<dim3(8, 16), 512, SMEM2>>>(
        x, (const float*)mt_ptr, out, coh);
}